// round 16
// baseline (speedup 1.0000x reference)
#include <cuda_runtime.h>
#include <cuda_bf16.h>
#include <math.h>
#include <stdint.h>

#define BDIM 64
#define TDIM 4096
#define CDIM 64
#define HDIM 64
#define WDIM 64
#define CONDD 16
#define HID 128
#define INDIM 81
#define NTOK 64
#define NTHREADS 256
#define PITCH2 264            // act row pitch: s cols [0,128), t at [136,264)
#define PITCH2_U32 132
#define TOFF 136
#define CPITCH 104            // comb row pitch (bf16)
#define CPITCH_U32 52
#define S_MAX 1.5f

#define NTOT (BDIM * TDIM)
#define ZSIZE ((size_t)NTOT * 2)

// ---------------- device scratch ----------------
__device__ float g_wT[(size_t)BDIM * HDIM * WDIM * CDIM];   // [b][y][x][c]
// B fragments in mma.sync lane order: [img(16)][ks(8)][n8(16)][lane(32)][reg(2)]
__device__ __align__(16) uint32_t g_WfH[16 * 8 * 16 * 64];
__device__ __align__(16) uint32_t g_WfL[16 * 8 * 16 * 64];

__device__ __forceinline__ float silu_f(float z) {
    return __fdividef(z, 1.0f + __expf(-z));
}
// quad silu: 4 ex2 + 1 rcp (vs 8 MUFU) via shared reciprocal
__device__ __forceinline__ void silu4(const float z[4], float o[4]) {
    float A0 = 1.0f + __expf(-z[0]);
    float A1 = 1.0f + __expf(-z[1]);
    float A2 = 1.0f + __expf(-z[2]);
    float A3 = 1.0f + __expf(-z[3]);
    float p1 = A0 * A1;
    float p2 = p1 * A2;
    float P  = p2 * A3;
    float r;
    asm("rcp.approx.f32 %0, %1;" : "=f"(r) : "f"(P));
    float s2 = A3 * A2;
    float s1 = s2 * A1;
    o[0] = z[0] * (r * s1);
    o[1] = z[1] * (r * A0 * s2);
    o[2] = z[2] * (r * p1 * A3);
    o[3] = z[3] * (r * p2);
}
__device__ __forceinline__ void ldsm_x4(uint32_t d[4], uint32_t saddr) {
    asm volatile("ldmatrix.sync.aligned.m8n8.x4.shared.b16 {%0,%1,%2,%3}, [%4];\n"
        : "=r"(d[0]), "=r"(d[1]), "=r"(d[2]), "=r"(d[3]) : "r"(saddr));
}
__device__ __forceinline__ void mma_bf16(float c[4], const uint32_t a[4],
                                         uint32_t b0, uint32_t b1) {
    asm volatile(
        "mma.sync.aligned.m16n8k16.row.col.f32.bf16.bf16.f32 "
        "{%0,%1,%2,%3}, {%4,%5,%6,%7}, {%8,%9}, {%0,%1,%2,%3};\n"
        : "+f"(c[0]), "+f"(c[1]), "+f"(c[2]), "+f"(c[3])
        : "r"(a[0]), "r"(a[1]), "r"(a[2]), "r"(a[3]), "r"(b0), "r"(b1));
}
__device__ __forceinline__ void group_bar(int id) {
    asm volatile("bar.sync %0, 128;" :: "r"(id) : "memory");
}
// pack (a,b) -> bf16x2 (a in low 16), residual pair likewise; 2 cvt total
__device__ __forceinline__ uint32_t bf16x2_rn(float a, float b) {
    uint32_t r;
    asm("cvt.rn.bf16x2.f32 %0, %1, %2;" : "=r"(r) : "f"(b), "f"(a));
    return r;
}
__device__ __forceinline__ void split_store_pair_p(uint32_t* H, uint32_t* L, int pitch_u32,
                                                   int row, int n0, float a, float b) {
    uint32_t hp = bf16x2_rn(a, b);
    float ra = a - __uint_as_float(hp << 16);
    float rb = b - __uint_as_float(hp & 0xFFFF0000u);
    uint32_t lp = bf16x2_rn(ra, rb);
    H[row * pitch_u32 + (n0 >> 1)] = hp;
    L[row * pitch_u32 + (n0 >> 1)] = lp;
}

// ---------------- prep: weights -> mma fragment order (bf16 hi/lo) ----------
__global__ void prep_kernel(const float* __restrict__ W0,
                            const float* __restrict__ W1,
                            float* __restrict__ out) {
    int idx = blockIdx.x * blockDim.x + threadIdx.x;   // 0..262143
    if (idx < 16 * 8 * 16 * 64) {
        int reg  = idx & 1;
        int lane = (idx >> 1) & 31;
        int n8   = (idx >> 6) & 15;
        int ks   = (idx >> 10) & 7;
        int img  = idx >> 13;                          // net*4 + l
        int net = img >> 2, l = img & 3;
        int n  = n8 * 8 + (lane >> 2);
        int k0 = ks * 16 + (lane & 3) * 2 + reg * 8;
        float v0 = 0.0f, v1 = 0.0f;
        if (l == 0) {
            // act k-order: [lf(0..63) | cond(64..79) | z(80) | pad]
            if (k0 <= 80)     v0 = W0[(net * HID + n) * INDIM + ((k0 < 80) ? (k0 + 1) : 0)];
            if (k0 + 1 <= 80) v1 = W0[(net * HID + n) * INDIM + ((k0 + 1 < 80) ? (k0 + 2) : 0)];
        } else {
            int g = net * 3 + (l - 1);
            v0 = W1[(g * HID + n) * HID + k0];
            v1 = W1[(g * HID + n) * HID + k0 + 1];
        }
        __nv_bfloat16 h0 = __float2bfloat16_rn(v0);
        __nv_bfloat16 h1 = __float2bfloat16_rn(v1);
        __nv_bfloat162 hp = __halves2bfloat162(h0, h1);
        __nv_bfloat162 lp = __halves2bfloat162(
            __float2bfloat16_rn(v0 - __bfloat162float(h0)),
            __float2bfloat16_rn(v1 - __bfloat162float(h1)));
        g_WfH[idx] = *reinterpret_cast<uint32_t*>(&hp);
        g_WfL[idx] = *reinterpret_cast<uint32_t*>(&lp);
    }
    if (idx < BDIM) out[ZSIZE + idx] = 0.0f;
}

// ---------------- transpose w [B,C,H,W] -> g_wT [B,H,W,C] ----------------
__global__ void transpose_w_kernel(const float* __restrict__ w) {
    __shared__ float tile[64][65];
    int by = blockIdx.x;
    int b = by / HDIM, y = by % HDIM;
    int tid = threadIdx.x;
    for (int i = tid; i < 64 * 64; i += NTHREADS) {
        int c = i >> 6, xq = i & 63;
        tile[c][xq] = w[(((size_t)b * CDIM + c) * HDIM + y) * WDIM + xq];
    }
    __syncthreads();
    for (int i = tid; i < 64 * 64; i += NTHREADS) {
        int xq = i >> 6, c = i & 63;
        g_wT[(((size_t)b * HDIM + y) * WDIM + xq) * CDIM + c] = tile[c][xq];
    }
}

// ---------------- phase kernel: fused s/t nets, decoupled pipelines ---------
template <int PHASE>
__global__ __launch_bounds__(NTHREADS, 2)
void phase_kernel(const float* __restrict__ x,
                  const float* __restrict__ cond,
                  const float* __restrict__ b0g,
                  const float* __restrict__ b1g,
                  const float* __restrict__ W2g,
                  const float* __restrict__ b2g,
                  float* __restrict__ out) {
    extern __shared__ char smraw[];
    __nv_bfloat16* combH = (__nv_bfloat16*)smraw;         // 64 x 104
    __nv_bfloat16* combL = combH + NTOK * CPITCH;
    __nv_bfloat16* actH  = combL + NTOK * CPITCH;         // 64 x 264
    __nv_bfloat16* actL  = actH + NTOK * PITCH2;
    float* sArr = (float*)(actL + NTOK * PITCH2);         // 64
    float* tArr = sArr + NTOK;                            // 64
    float* w2sm = tArr + NTOK;                            // 256 (s | t)

    const int tid = threadIdx.x;
    const int lane = tid & 31;
    const int wid = tid >> 5;
    const int wnet = wid >> 2;                 // 0 = s-group, 1 = t-group
    const int w4 = wid & 3;
    const int n8base = w4 * 4;
    const int nbase = blockIdx.x * NTOK;
    const int b = nbase >> 12;

    uint32_t combH_s = (uint32_t)__cvta_generic_to_shared(combH);
    uint32_t combL_s = (uint32_t)__cvta_generic_to_shared(combL);
    uint32_t actH_s  = (uint32_t)__cvta_generic_to_shared(actH);
    uint32_t actL_s  = (uint32_t)__cvta_generic_to_shared(actL);
    uint32_t* combH_u = (uint32_t*)combH;
    uint32_t* combL_u = (uint32_t*)combL;
    uint32_t* actH_u = (uint32_t*)actH;
    uint32_t* actL_u = (uint32_t*)actL;

    const int r8 = lane & 7;
    const int gA = (lane >> 3) & 1;
    const int gB = lane >> 4;

    const int base_net = (PHASE == 1) ? 0 : 2;
    const int net = base_net + wnet;
    const int netColOff = wnet ? TOFF : 0;

    // ---- gather: 4 threads per token, 16 lf channels each -> comb ----
    {
        int tk = tid >> 2;
        int q4 = tid & 3;
        int n = nbase + tk;
        float zx, zy, zkeep;
        if (PHASE == 1) { zx = x[2 * n]; zy = x[2 * n + 1]; zkeep = zy; }
        else            { zx = out[2 * n]; zy = x[2 * n + 1]; zkeep = zx; }
        float ix = zx * 63.0f, iy = zy * 63.0f;
        float ix0 = floorf(ix), iy0 = floorf(iy);
        float wx1 = ix - ix0, wx0 = 1.0f - wx1;
        float wy1 = iy - iy0, wy0 = 1.0f - wy1;
        float acc[16];
#pragma unroll
        for (int c = 0; c < 16; c++) acc[c] = 0.0f;
#pragma unroll
        for (int corner = 0; corner < 4; corner++) {
            int dx = corner & 1, dy = corner >> 1;
            float xx = ix0 + (float)dx, yy = iy0 + (float)dy;
            if (xx >= 0.0f && xx <= 63.0f && yy >= 0.0f && yy <= 63.0f) {
                float wgt = (dx ? wx1 : wx0) * (dy ? wy1 : wy0);
                const float4* gp = (const float4*)(g_wT +
                    (((size_t)b * HDIM + (int)yy) * WDIM + (int)xx) * CDIM + q4 * 16);
#pragma unroll
                for (int q = 0; q < 4; q++) {
                    float4 v = gp[q];
                    acc[q * 4 + 0] += wgt * v.x;
                    acc[q * 4 + 1] += wgt * v.y;
                    acc[q * 4 + 2] += wgt * v.z;
                    acc[q * 4 + 3] += wgt * v.w;
                }
            }
        }
#pragma unroll
        for (int c = 0; c < 8; c++)
            split_store_pair_p(combH_u, combL_u, CPITCH_U32, tk, q4 * 16 + 2 * c,
                               acc[2 * c], acc[2 * c + 1]);
        if (q4 == 0) {
#pragma unroll
            for (int j = 0; j < 8; j++) {
                float c0 = cond[b * CONDD + 2 * j];
                float c1 = cond[b * CONDD + 2 * j + 1];
                split_store_pair_p(combH_u, combL_u, CPITCH_U32, tk, 64 + 2 * j, c0, c1);
            }
        } else if (q4 == 1) {
            split_store_pair_p(combH_u, combL_u, CPITCH_U32, tk, 80, zkeep, 0.0f);
#pragma unroll
            for (int q = 41; q < 48; q++) {
                combH_u[tk * CPITCH_U32 + q] = 0u;
                combL_u[tk * CPITCH_U32 + q] = 0u;
            }
        }
    }
    if (tid < 2 * HID) {
        int wh = tid >> 7;
        w2sm[tid] = W2g[(base_net + wh) * HID + (tid & 127)];
    }
    if (tid < NTOK) { sArr[tid] = 0.0f; tArr[tid] = 0.0f; }
    __syncthreads();

    // ---- 4 layers; group-local barriers only ----
    for (int l = 0; l < 4; ++l) {
        const int img = net * 4 + l;
        const int ksteps = (l == 0) ? 6 : 8;
        const float* bias = (l == 0) ? (b0g + net * HID)
                                     : (b1g + (net * 3 + (l - 1)) * HID);

        float acc[4][4][4];
#pragma unroll
        for (int mi = 0; mi < 4; mi++)
#pragma unroll
            for (int t = 0; t < 4; t++)
#pragma unroll
                for (int q = 0; q < 4; q++) acc[mi][t][q] = 0.0f;

#pragma unroll 2
        for (int ks = 0; ks < ksteps; ++ks) {
            uint2 bh[4], bl[4];
#pragma unroll
            for (int t = 0; t < 4; t++) {
                int off = (((img * 8 + ks) * 16 + n8base + t) << 6) + lane * 2;
                bh[t] = *(const uint2*)&g_WfH[off];
                bl[t] = *(const uint2*)&g_WfL[off];
            }
#pragma unroll
            for (int mi = 0; mi < 4; mi++) {
                uint32_t aH[4], aL[4];
                if (l == 0) {
                    int colA = ks * 16 + gB * 8;
                    uint32_t offA = (uint32_t)(((mi * 16 + r8 + gA * 8) * CPITCH + colA) * 2);
                    ldsm_x4(aH, combH_s + offA);
                    ldsm_x4(aL, combL_s + offA);
                } else {
                    int colA = netColOff + ks * 16 + gB * 8;
                    uint32_t offA = (uint32_t)(((mi * 16 + r8 + gA * 8) * PITCH2 + colA) * 2);
                    ldsm_x4(aH, actH_s + offA);
                    ldsm_x4(aL, actL_s + offA);
                }
#pragma unroll
                for (int t = 0; t < 4; t++) {
                    float* c4 = acc[mi][t];
                    mma_bf16(c4, aH, bh[t].x, bh[t].y);
                    mma_bf16(c4, aH, bl[t].x, bl[t].y);
                    mma_bf16(c4, aL, bh[t].x, bh[t].y);
                }
            }
        }

        if (l < 3) {
            if (l > 0) group_bar(1 + wnet);   // group's act reads done
            // epilogue: bias + quad-silu -> split bf16 -> own act region
#pragma unroll
            for (int t = 0; t < 4; t++) {
                int nn = n8base * 8 + t * 8 + (lane & 3) * 2;
                float2 bb = *(const float2*)&bias[nn];
                int cc = netColOff + nn;
#pragma unroll
                for (int mi = 0; mi < 4; mi++) {
                    int row0 = mi * 16 + (lane >> 2);
                    float* d = acc[mi][t];
                    float zin[4] = { d[0] + bb.x, d[1] + bb.y, d[2] + bb.x, d[3] + bb.y };
                    float h[4];
                    silu4(zin, h);
                    split_store_pair_p(actH_u, actL_u, PITCH2_U32, row0, cc, h[0], h[1]);
                    split_store_pair_p(actH_u, actL_u, PITCH2_U32, row0 + 8, cc, h[2], h[3]);
                }
            }
            group_bar(1 + wnet);              // writes visible to group
        } else {
            // ---- layer 3: fused dot epilogue (no act writes) ----
            float pA[4], pB[4];
#pragma unroll
            for (int mi = 0; mi < 4; mi++) { pA[mi] = 0.0f; pB[mi] = 0.0f; }
            const float* w2 = w2sm + wnet * HID;
#pragma unroll
            for (int t = 0; t < 4; t++) {
                int nn = n8base * 8 + t * 8 + (lane & 3) * 2;
                float2 bb = *(const float2*)&bias[nn];
                float2 ww = *(const float2*)&w2[nn];
#pragma unroll
                for (int mi = 0; mi < 4; mi++) {
                    float* d = acc[mi][t];
                    float zin[4] = { d[0] + bb.x, d[1] + bb.y, d[2] + bb.x, d[3] + bb.y };
                    float h[4];
                    silu4(zin, h);
                    pA[mi] += h[0] * ww.x + h[1] * ww.y;
                    pB[mi] += h[2] * ww.x + h[3] * ww.y;
                }
            }
            float* dst = wnet ? tArr : sArr;
#pragma unroll
            for (int mi = 0; mi < 4; mi++) {
                pA[mi] += __shfl_xor_sync(0xffffffffu, pA[mi], 1);
                pA[mi] += __shfl_xor_sync(0xffffffffu, pA[mi], 2);
                pB[mi] += __shfl_xor_sync(0xffffffffu, pB[mi], 1);
                pB[mi] += __shfl_xor_sync(0xffffffffu, pB[mi], 2);
                if ((lane & 3) == 0) {
                    int row = mi * 16 + (lane >> 2);
                    atomicAdd(&dst[row], pA[mi]);
                    atomicAdd(&dst[row + 8], pB[mi]);
                }
            }
        }
    }
    __syncthreads();   // both groups' dot atomics visible

    // ---- coupling update + log_det ----
    if (tid < NTOK) {
        int n = nbase + tid;
        float s = tanhf(sArr[tid] + b2g[base_net]) * S_MAX;
        float t = tArr[tid] + b2g[base_net + 1];
        float zold = (PHASE == 1) ? x[2 * n] : x[2 * n + 1];
        out[2 * n + ((PHASE == 1) ? 0 : 1)] = zold * expf(s) + t;
        sArr[tid] = s;
    }
    __syncthreads();
    if (tid < 32) {
        float v = sArr[tid] + sArr[tid + 32];
#pragma unroll
        for (int off = 16; off > 0; off >>= 1) v += __shfl_down_sync(0xffffffffu, v, off);
        if (tid == 0) atomicAdd(out + ZSIZE + b, v);
    }
}

// ---------------- launch ----------------
extern "C" void kernel_launch(void* const* d_in, const int* in_sizes, int n_in,
                              void* d_out, int out_size) {
    const float* x    = (const float*)d_in[0];
    const float* w    = (const float*)d_in[1];
    const float* cond = (const float*)d_in[2];
    const float* W0   = (const float*)d_in[3];
    const float* b0   = (const float*)d_in[4];
    const float* W1   = (const float*)d_in[5];
    const float* b1   = (const float*)d_in[6];
    const float* W2   = (const float*)d_in[7];
    const float* b2   = (const float*)d_in[8];
    float* out = (float*)d_out;

    const size_t smem = (size_t)(2 * NTOK * CPITCH) * 2 +      // combH/L
                        (size_t)(2 * NTOK * PITCH2) * 2 +      // actH/L
                        (size_t)(2 * NTOK + 2 * HID) * 4;      // sArr, tArr, w2sm
    cudaFuncSetAttribute(phase_kernel<1>, cudaFuncAttributeMaxDynamicSharedMemorySize, (int)smem);
    cudaFuncSetAttribute(phase_kernel<2>, cudaFuncAttributeMaxDynamicSharedMemorySize, (int)smem);

    prep_kernel<<<1024, NTHREADS>>>(W0, W1, out);
    transpose_w_kernel<<<BDIM * HDIM, NTHREADS>>>(w);
    phase_kernel<1><<<NTOT / NTOK, NTHREADS, smem>>>(x, cond, b0, b1, W2, b2, out);
    phase_kernel<2><<<NTOT / NTOK, NTHREADS, smem>>>(x, cond, b0, b1, W2, b2, out);
}